// round 7
// baseline (speedup 1.0000x reference)
#include <cuda_runtime.h>
#include <cstdint>

// Problem constants
#define NB     16
#define NFREQ  513
#define NT     4000
#define NFFT   1024
#define HOP    256
#define OUT_PER_B (3999 * 256)   // 1023744

#define THREADS 256
#define G_HOPS  13               // output hops per block
#define NFRAMES 16               // frames per block (13 + 3 halo)
#define CHUNK   (G_HOPS * HOP)   // 3328 samples per block
#define NCHUNK  ((OUT_PER_B + CHUNK - 1) / CHUNK)   // 308

#define FROW    1056             // skewed frame row stride (floats)
#define STG_STRIDE 522           // staging stride (float2) per frame

// SMEM layout (floats):
//  fbuf: NFRAMES * FROW            = 16896
//  stg : 8 * STG_STRIDE * 2        =  8352
//  tw  : 512 float2                =  1024
//  win : 1056                      =  1056
#define SM_FBUF 0
#define SM_STG  (SM_FBUF + NFRAMES * FROW)
#define SM_TW   (SM_STG + 8 * STG_STRIDE * 2)
#define SM_WIN  (SM_TW + 1024)
#define SM_FLOATS (SM_WIN + 1056)
#define SMEM_BYTES (SM_FLOATS * 4)

// Twiddle table e^{+2*pi*i*j/1024}, j = 0..511
__device__ float2 g_tw[512];

// e^{+2*pi*i*j/32}
__constant__ float W32C[32] = {
     1.000000000f,  0.980785280f,  0.923879533f,  0.831469612f,
     0.707106781f,  0.555570233f,  0.382683432f,  0.195090322f,
     0.000000000f, -0.195090322f, -0.382683432f, -0.555570233f,
    -0.707106781f, -0.831469612f, -0.923879533f, -0.980785280f,
    -1.000000000f, -0.980785280f, -0.923879533f, -0.831469612f,
    -0.707106781f, -0.555570233f, -0.382683432f, -0.195090322f,
     0.000000000f,  0.195090322f,  0.382683432f,  0.555570233f,
     0.707106781f,  0.831469612f,  0.923879533f,  0.980785280f
};
__constant__ float W32S[32] = {
     0.000000000f,  0.195090322f,  0.382683432f,  0.555570233f,
     0.707106781f,  0.831469612f,  0.923879533f,  0.980785280f,
     1.000000000f,  0.980785280f,  0.923879533f,  0.831469612f,
     0.707106781f,  0.555570233f,  0.382683432f,  0.195090322f,
     0.000000000f, -0.195090322f, -0.382683432f, -0.555570233f,
    -0.707106781f, -0.831469612f, -0.923879533f, -0.980785280f,
    -1.000000000f, -0.980785280f, -0.923879533f, -0.831469612f,
    -0.707106781f, -0.555570233f, -0.382683432f, -0.195090322f
};

__global__ void tw_init_kernel() {
    int j = blockIdx.x * 256 + threadIdx.x;   // grid covers 512
    if (j < 512) {
        float s, c;
        sincospif((float)j * (1.0f / 512.0f), &s, &c);   // 2*pi*j/1024
        g_tw[j] = make_float2(c, s);
    }
}

__device__ __forceinline__ float2 cmul(float2 a, float2 b) {
    return make_float2(a.x * b.x - a.y * b.y, a.x * b.y + a.y * b.x);
}

// ---------------------------------------------------------------------------
// 16-point inverse DFT in registers (radix-4 x radix-4), no 1/N scaling.
// ---------------------------------------------------------------------------
__device__ __forceinline__ void ifft16(float2 v[16]) {
    float2 g[16];
#pragma unroll
    for (int j1 = 0; j1 < 4; j1++) {
        float2 a = v[j1], b = v[j1 + 4], c = v[j1 + 8], d = v[j1 + 12];
        float t0x = a.x + c.x, t0y = a.y + c.y;
        float t1x = a.x - c.x, t1y = a.y - c.y;
        float t2x = b.x + d.x, t2y = b.y + d.y;
        float t3x = b.x - d.x, t3y = b.y - d.y;
        g[j1 * 4 + 0] = make_float2(t0x + t2x, t0y + t2y);
        g[j1 * 4 + 1] = make_float2(t1x - t3y, t1y + t3x);
        g[j1 * 4 + 2] = make_float2(t0x - t2x, t0y - t2y);
        g[j1 * 4 + 3] = make_float2(t1x + t3y, t1y - t3x);
    }
#pragma unroll
    for (int j1 = 1; j1 < 4; j1++) {
#pragma unroll
        for (int m2 = 1; m2 < 4; m2++) {
            float wc = W32C[2 * j1 * m2];
            float ws = W32S[2 * j1 * m2];
            float2 x = g[j1 * 4 + m2];
            g[j1 * 4 + m2] = make_float2(x.x * wc - x.y * ws, x.x * ws + x.y * wc);
        }
    }
#pragma unroll
    for (int m2 = 0; m2 < 4; m2++) {
        float2 a = g[m2], b = g[4 + m2], c = g[8 + m2], d = g[12 + m2];
        float t0x = a.x + c.x, t0y = a.y + c.y;
        float t1x = a.x - c.x, t1y = a.y - c.y;
        float t2x = b.x + d.x, t2y = b.y + d.y;
        float t3x = b.x - d.x, t3y = b.y - d.y;
        v[m2 + 0]  = make_float2(t0x + t2x, t0y + t2y);
        v[m2 + 4]  = make_float2(t1x - t3y, t1y + t3x);
        v[m2 + 8]  = make_float2(t0x - t2x, t0y - t2y);
        v[m2 + 12] = make_float2(t1x + t3y, t1y - t3x);
    }
}

// ---------------------------------------------------------------------------
// Fused kernel: per-chunk frame IFFTs into SMEM + overlap-add + normalize
// grid = (NCHUNK, NB), block = 256 (8 warps)
// ---------------------------------------------------------------------------
__global__ void __launch_bounds__(THREADS, 2)
istft_fused_kernel(const float* __restrict__ mag,
                   const float* __restrict__ cosp,
                   const float* __restrict__ sinp,
                   const float* __restrict__ window,
                   float* __restrict__ out) {
    extern __shared__ float smem[];
    float*  fbuf  = smem + SM_FBUF;
    float2* stg   = reinterpret_cast<float2*>(smem + SM_STG);
    float2* tw    = reinterpret_cast<float2*>(smem + SM_TW);
    float*  win_s = smem + SM_WIN;

    const int tid  = threadIdx.x;
    const int w    = tid >> 5;
    const int lane = tid & 31;
    const int c    = blockIdx.x;
    const int b    = blockIdx.y;
    const int ft0  = G_HOPS * c - 1;                 // first frame slot's t

    // block-wide tables
    for (int j = tid; j < 512; j += THREADS) tw[j] = g_tw[j];
    for (int j = tid; j < 1024; j += THREADS) win_s[j + (j >> 5)] = window[j];

    const size_t bbase = (size_t)b * NFREQ * NT;
    const float inv_n = 1.0f / 1024.0f;
    const int n1 = __brev(lane) >> 27;               // bitrev5(lane)

    // ---- two rounds: stage 8 frames, FFT 8 frames ----
#pragma unroll 1
    for (int r = 0; r < 2; r++) {
        // stage: t_off in [0,8) -> frame slot r*8+t_off
        {
            const int t_off = tid & 7;
            const int f_off = tid >> 3;
            const int t = ft0 + r * 8 + t_off;
            if (t >= 0 && t < NT) {
                float2* Sld = stg + t_off * STG_STRIDE;
                const size_t base = bbase + (size_t)t;
                for (int f = f_off; f < NFREQ; f += 32) {
                    size_t idx = base + (size_t)f * NT;
                    float m  = mag[idx];
                    float cp = cosp[idx];
                    float sn = sinp[idx];
                    Sld[f] = make_float2(m * cp, m * sn);
                }
            }
        }
        __syncthreads();

        // FFT: warp w handles slot r*8+w
        const int slot = r * 8 + w;
        const int t = ft0 + slot;
        if (t >= 0 && t < NT) {
            const float2* H = stg + w * STG_STRIDE;

            // Z[k] = (H[k]+conj(H[512-k])) + i*W1024^k*(H[k]-conj(H[512-k]))
            float2 v[16];
#pragma unroll
            for (int k2 = 0; k2 < 16; k2++) {
                const int k = lane + (k2 << 5);
                float2 a  = H[k];
                float2 bb = H[512 - k];
                if (k == 0) { a.y = 0.0f; bb.y = 0.0f; }
                float qx = a.x - bb.x;
                float qy = a.y + bb.y;
                float2 W = tw[k < 512 ? k : 0];      // k max is 511 except k2=0 path
                if (k == 0) W = make_float2(1.0f, 0.0f);
                v[k2].x = (a.x + bb.x) - (W.x * qy + W.y * qx);
                v[k2].y = (a.y - bb.y) + (W.x * qx - W.y * qy);
            }

            ifft16(v);                               // k2 -> n2

            // twiddle e^{2*pi*i*n2*lane/512} via power recurrence (bank-conflict-free)
            {
                float2 Wb = tw[2 * lane];            // e^{2*pi*i*(2*lane)/1024}
                float2 Wc = Wb;
#pragma unroll
                for (int n2 = 1; n2 < 16; n2++) {
                    v[n2] = cmul(v[n2], Wc);
                    if (n2 < 15) Wc = cmul(Wc, Wb);
                }
            }

            // cross-lane 32-pt inverse DIF over lanes
#pragma unroll
            for (int s = 0; s < 5; s++) {
                const int h = 16 >> s;
                const float wc = W32C[(lane & (h - 1)) << s];
                const float ws = W32S[(lane & (h - 1)) << s];
                const bool hi = (lane & h) != 0;
#pragma unroll
                for (int n2 = 0; n2 < 16; n2++) {
                    float px = __shfl_xor_sync(0xffffffffu, v[n2].x, h);
                    float py = __shfl_xor_sync(0xffffffffu, v[n2].y, h);
                    float2 rr;
                    if (hi) {
                        float dx = px - v[n2].x;
                        float dy = py - v[n2].y;
                        rr = make_float2(dx * wc - dy * ws, dx * ws + dy * wc);
                    } else {
                        rr = make_float2(v[n2].x + px, v[n2].y + py);
                    }
                    v[n2] = rr;
                }
            }

            // windowed store to skewed SMEM frame row:
            // lane owns samples n = 32*n1 + {2*n2, 2*n2+1}
            float* frow = fbuf + slot * FROW;
            const int bidx = 33 * n1;                // 32*n1 + (32*n1>>5)
#pragma unroll
            for (int q = 0; q < 8; q++) {
                const int i0 = bidx + 4 * q;
                frow[i0 + 0] = v[2 * q].x     * win_s[i0 + 0] * inv_n;
                frow[i0 + 1] = v[2 * q].y     * win_s[i0 + 1] * inv_n;
                frow[i0 + 2] = v[2 * q + 1].x * win_s[i0 + 2] * inv_n;
                frow[i0 + 3] = v[2 * q + 1].y * win_s[i0 + 3] * inv_n;
            }
        }
        __syncthreads();
    }

    // ---- overlap-add + envelope normalize + trim ----
    const int j0 = c * CHUNK;
    float* outb = out + (size_t)b * OUT_PER_B;
#pragma unroll 1
    for (int i = 0; i < G_HOPS; i++) {
        const int j = j0 + i * HOP + tid;
        if (j >= OUT_PER_B) break;
        const int s = j + NFFT / 2;
        int thi = s >> 8; if (thi > NT - 1) thi = NT - 1;
        int tlo = (s - 768) >> 8; if (tlo < 0) tlo = 0;

        float acc = 0.0f, env = 0.0f;
#pragma unroll 4
        for (int t = tlo; t <= thi; t++) {
            const int n  = s - (t << 8);             // [0,1023]
            const int ni = n + (n >> 5);
            acc += fbuf[(t - ft0) * FROW + ni];
            float wv = win_s[ni];
            env += wv * wv;
        }
        outb[j] = acc / (env + 1e-11f);
    }
}

// ---------------------------------------------------------------------------
extern "C" void kernel_launch(void* const* d_in, const int* in_sizes, int n_in,
                              void* d_out, int out_size) {
    const float* mag    = (const float*)d_in[0];
    const float* cosp   = (const float*)d_in[1];
    const float* sinp   = (const float*)d_in[2];
    const float* window = (const float*)d_in[3];
    float* out = (float*)d_out;

    cudaFuncSetAttribute(istft_fused_kernel,
                         cudaFuncAttributeMaxDynamicSharedMemorySize, SMEM_BYTES);

    tw_init_kernel<<<2, 256>>>();

    dim3 grid(NCHUNK, NB);   // 308 x 16
    istft_fused_kernel<<<grid, THREADS, SMEM_BYTES>>>(mag, cosp, sinp, window, out);
}